// round 3
// baseline (speedup 1.0000x reference)
#include <cuda_runtime.h>

// Problem constants
#define K_COLORS 512
#define HW       65536            // 256*256
#define B        8
#define PPT      8                // one pixel per batch image per thread
#define NPAIR    (PPT / 2)
#define NTHREADS 64
#define NBLOCKS  1024             // NTHREADS*NBLOCKS = 65536 = HW
#define NPIX     (HW * B)         // 524288
#define NOUT     (NPIX * 3)       // 1572864

__device__ float        g_partials[NBLOCKS];
__device__ unsigned int g_count = 0;

// ---- packed f32x2 helpers (Blackwell PTX-only ops) ----
__device__ __forceinline__ unsigned long long fma2(unsigned long long a,
                                                   unsigned long long b,
                                                   unsigned long long c) {
    unsigned long long d;
    asm("fma.rn.f32x2 %0, %1, %2, %3;" : "=l"(d) : "l"(a), "l"(b), "l"(c));
    return d;
}
__device__ __forceinline__ unsigned long long pk2(float lo, float hi) {
    unsigned long long r;
    asm("mov.b64 %0, {%1, %2};" : "=l"(r)
        : "r"(__float_as_uint(lo)), "r"(__float_as_uint(hi)));
    return r;
}
__device__ __forceinline__ unsigned long long bc2(float x) {
    unsigned int u = __float_as_uint(x);
    return ((unsigned long long)u << 32) | u;
}
__device__ __forceinline__ float lo_f(unsigned long long v) {
    return __uint_as_float((unsigned int)v);
}
__device__ __forceinline__ float hi_f(unsigned long long v) {
    return __uint_as_float((unsigned int)(v >> 32));
}

// Fused VQ + straight-through output + loss.
// Each thread owns one (h,w) position across all 8 batch images (coalesced
// stride-3*HW accesses in the [B,3,H,W] layout).
// Palette pre-broadcast in smem: scA[k] = {(-2t0,-2t0),(-2t1,-2t1)},
// scB[k] = {(-2t2,-2t2),(t2sum,t2sum)}.
// Inner loop per (k, pixel-pair): d = fma2^3 (same chain order/rounding as a
// scalar fmaf chain); per half: exact strict '<' compare keeps the FIRST
// index on ties (matches jnp.argmin); value via fminf, index via select.
__global__ void __launch_bounds__(NTHREADS) vq_kernel(
    const float* __restrict__ z,
    const float* __restrict__ table,
    float* __restrict__ out,
    int out_size)
{
    __shared__ ulonglong2 scA[K_COLORS];
    __shared__ ulonglong2 scB[K_COLORS];
    __shared__ float      sred[NTHREADS];
    __shared__ int        s_last;

    const int tid = threadIdx.x;

    for (int k = tid; k < K_COLORS; k += NTHREADS) {
        float t0 = table[3 * k + 0];
        float t1 = table[3 * k + 1];
        float t2 = table[3 * k + 2];
        float n  = __fadd_rn(__fadd_rn(__fmul_rn(t0, t0), __fmul_rn(t1, t1)),
                             __fmul_rn(t2, t2));
        scA[k] = make_ulonglong2(bc2(-2.0f * t0), bc2(-2.0f * t1));
        scB[k] = make_ulonglong2(bc2(-2.0f * t2), bc2(n));
    }
    __syncthreads();

    const int g = blockIdx.x * NTHREADS + tid;   // hw index, 0..65535

    unsigned long long X[NPAIR], Y[NPAIR], Z[NPAIR];
#pragma unroll
    for (int j = 0; j < NPAIR; ++j) {
        const int b0 = (2 * j) * 3 * HW + g;
        const int b1 = (2 * j + 1) * 3 * HW + g;
        X[j] = pk2(z[b0],          z[b1]);
        Y[j] = pk2(z[b0 + HW],     z[b1 + HW]);
        Z[j] = pk2(z[b0 + 2 * HW], z[b1 + 2 * HW]);
    }

    float bestv[PPT];
    int   bidx[PPT];
#pragma unroll
    for (int p = 0; p < PPT; ++p) {
        bestv[p] = 3.402823466e38f;
        bidx[p]  = 0;
    }

#pragma unroll 4
    for (int k = 0; k < K_COLORS; ++k) {
        const ulonglong2 ca = scA[k];
        const ulonglong2 cb = scB[k];
#pragma unroll
        for (int j = 0; j < NPAIR; ++j) {
            // d = x*(-2t0) + (y*(-2t1) + (z*(-2t2) + t2sum))
            unsigned long long acc = fma2(Z[j], cb.x, cb.y);
            acc = fma2(Y[j], ca.y, acc);
            acc = fma2(X[j], ca.x, acc);
            float dlo = lo_f(acc);
            float dhi = hi_f(acc);
            bool l0 = dlo < bestv[2 * j];
            bool l1 = dhi < bestv[2 * j + 1];
            bestv[2 * j]     = fminf(bestv[2 * j],     dlo);   // FMNMX (fma pipe)
            bestv[2 * j + 1] = fminf(bestv[2 * j + 1], dhi);
            bidx[2 * j]      = l0 ? k : bidx[2 * j];           // SEL (alu pipe)
            bidx[2 * j + 1]  = l1 ? k : bidx[2 * j + 1];
        }
    }

    // Epilogue: recover exact palette color from -2t (multiply by -0.5 is
    // exact), mirror reference STE rounding, accumulate squared error.
    float lsum = 0.0f;
#pragma unroll
    for (int p = 0; p < PPT; ++p) {
        const int bi = bidx[p];
        const ulonglong2 ca = scA[bi];
        const ulonglong2 cb = scB[bi];
        float q0 = -0.5f * lo_f(ca.x);
        float q1 = -0.5f * lo_f(ca.y);
        float q2 = -0.5f * lo_f(cb.x);
        float px = (p & 1) ? hi_f(X[p >> 1]) : lo_f(X[p >> 1]);
        float py = (p & 1) ? hi_f(Y[p >> 1]) : lo_f(Y[p >> 1]);
        float pz = (p & 1) ? hi_f(Z[p >> 1]) : lo_f(Z[p >> 1]);
        float d0 = __fsub_rn(q0, px);
        float d1 = __fsub_rn(q1, py);
        float d2 = __fsub_rn(q2, pz);
        const int base = p * 3 * HW + g;
        out[base]          = __fadd_rn(px, d0);          // zl + (z_q - zl)
        out[base + HW]     = __fadd_rn(py, d1);
        out[base + 2 * HW] = __fadd_rn(pz, d2);
        lsum = fmaf(d0, d0, lsum);
        lsum = fmaf(d1, d1, lsum);
        lsum = fmaf(d2, d2, lsum);
    }

    // Deterministic block reduction.
    sred[tid] = lsum;
    __syncthreads();
#pragma unroll
    for (int s = NTHREADS / 2; s > 0; s >>= 1) {
        if (tid < s) sred[tid] += sred[tid + s];
        __syncthreads();
    }

    // Last-block-done final reduction (single fused kernel; no 2nd launch).
    if (tid == 0) {
        g_partials[blockIdx.x] = sred[0];
        __threadfence();
        unsigned int prev = atomicAdd(&g_count, 1u);
        s_last = (prev == NBLOCKS - 1) ? 1 : 0;
    }
    __syncthreads();

    if (s_last) {
        __threadfence();
        volatile float* vp = g_partials;
        float acc = 0.0f;
        for (int i = tid; i < NBLOCKS; i += NTHREADS) acc += vp[i];
        sred[tid] = acc;
        __syncthreads();
#pragma unroll
        for (int s = NTHREADS / 2; s > 0; s >>= 1) {
            if (tid < s) sred[tid] += sred[tid + s];
            __syncthreads();
        }
        if (tid == 0) {
            float m    = sred[0] / (float)NOUT;
            float loss = __fadd_rn(10.0f * m, m);
            for (int i = NOUT; i < out_size; ++i) out[i] = loss;
            g_count = 0;   // reset for the next graph replay
        }
    }
}

extern "C" void kernel_launch(void* const* d_in, const int* in_sizes, int n_in,
                              void* d_out, int out_size)
{
    const float* z     = (const float*)d_in[0];
    const float* table = (const float*)d_in[1];
    float* out         = (float*)d_out;

    vq_kernel<<<NBLOCKS, NTHREADS>>>(z, table, out, out_size);
}